// round 14
// baseline (speedup 1.0000x reference)
#include <cuda_runtime.h>
#include <cuda_bf16.h>

#define K_ 16
#define P_ 27000
#define KG 2                      // k values per block

// Tile: x[b, c=0..2, h0:h0+3, 0:32, 0:32], strides c=3072,h=1024,w=32,d=1
#define TILE_F 9216
#define DYN_BYTES (TILE_F * 4)    // 36864 B dynamic smem

__constant__ float c_MOPS[64] = {
    0,0,0,0,   0,0,0,1,   0,1,0,-1,  0,1,0,0,
    0,0,1,-1,  0,0,1,0,   0,1,1,-2,  0,1,1,-1,
    1,-1,-1,1, 1,-1,-1,2, 1,0,-1,0,  1,0,-1,1,
    1,-1,0,0,  1,-1,0,1,  1,0,0,-1,  1,0,0,0
};

// c0 + c1*a + c2*b + c3*a*b = fma(b, fma(c3,a,c2), fma(c1,a,c0))
__device__ __forceinline__ float node_op(float4 c, float a, float b) {
    return fmaf(b, fmaf(c.w, a, c.z), fmaf(c.y, a, c.x));
}

extern __shared__ float s_tile[];   // 9216 floats

__global__ __launch_bounds__(256, 4)
void logic_fused(const float* __restrict__ x,
                 const int* __restrict__ ia, const int* __restrict__ ib,
                 const float* __restrict__ w0, const float* __restrict__ w1,
                 const float* __restrict__ w2, const float* __restrict__ w3,
                 const float* __restrict__ w4,
                 float* __restrict__ out)
{
    __shared__ float4 s_coef[KG][31];
    __shared__ int2   s_lin[KG][16];

    const int h0 = blockIdx.x;            // 0..29
    const int kg = blockIdx.y;            // 0..7 -> k = 2*kg + kk
    const int b  = blockIdx.z;            // 0..3
    const int t  = threadIdx.x;

    // ---- prep: tree coefficients for both k's (threads 0..61) ----
    if (t < KG * 31) {
        int kk   = (t >= 31);
        int node = t - 31 * kk;
        int k    = KG * kg + kk;
        const float* wp; int n;
        if      (node < 16) { wp = w0; n = node;      }
        else if (node < 24) { wp = w1; n = node - 16; }
        else if (node < 28) { wp = w2; n = node - 24; }
        else if (node < 30) { wp = w3; n = node - 28; }
        else                { wp = w4; n = 0;         }
        const float* row = wp + (n * K_ + k) * 16;
        float r[16];
        float m = -1e30f;
        #pragma unroll
        for (int o = 0; o < 16; o++) { r[o] = row[o]; m = fmaxf(m, r[o]); }
        float sum = 0.f;
        #pragma unroll
        for (int o = 0; o < 16; o++) { r[o] = __expf(r[o] - m); sum += r[o]; }
        float inv = 1.0f / sum;
        float c0 = 0.f, c1 = 0.f, c2 = 0.f, c3 = 0.f;
        #pragma unroll
        for (int o = 0; o < 16; o++) {
            float p = r[o] * inv;
            c0 = fmaf(p, c_MOPS[4*o + 0], c0);
            c1 = fmaf(p, c_MOPS[4*o + 1], c1);
            c2 = fmaf(p, c_MOPS[4*o + 2], c2);
            c3 = fmaf(p, c_MOPS[4*o + 3], c3);
        }
        s_coef[kk][node] = make_float4(c0, c1, c2, c3);
    }
    // ---- prep: leaf offsets for both k's (threads 64..127) ----
    if (t >= 64 && t < 64 + KG * 32) {
        int u   = t - 64;               // 0..63
        int kk  = u >> 5;               // 0..1
        int v   = u & 31;
        int isB = v >> 4;
        int s   = v & 15;
        int k   = KG * kg + kk;
        const int* src = isB ? ib : ia;
        int base = (k * P_ * 16 + s) * 4;
        int h = src[base + 0];
        int w = src[base + 1];
        int d = src[base + 2];
        int c = src[base + 3];
        int lin = c * 3072 + h * 1024 + w * 32 + d;   // tile-space offset
        if (isB) s_lin[kk][s].y = lin;
        else     s_lin[kk][s].x = lin;
    }

    // ---- tile load: 3 contiguous 3072-float slabs, pure float4 copies ----
    {
        const float* src = x + b * 98304 + h0 * 1024;   // x[b,0,h0,0,0]
        #pragma unroll
        for (int c = 0; c < 3; c++) {
            #pragma unroll
            for (int j = 0; j < 3; j++) {
                int e = (j * 256 + t) * 4;
                float4 v = *reinterpret_cast<const float4*>(src + c * 32768 + e);
                *reinterpret_cast<float4*>(s_tile + c * 3072 + e) = v;
            }
        }
    }
    __syncthreads();

    // ---- compute: lane = ld, rows warp + 8*o; repeat for kk = 0,1 ----
    const int lane = t & 31;
    const int warp = t >> 5;
    const int ld   = min(lane, 29);

    int bases[4];
    #pragma unroll
    for (int o = 0; o < 4; o++) {
        int lw = min(warp + 8 * o, 29);
        bases[o] = lw * 32 + ld;
    }

    float* outb = out + (b * K_ + KG * kg) * P_ + h0 * 900;

    #pragma unroll
    for (int kk = 0; kk < KG; kk++) {
        const float4* cf = s_coef[kk];
        const int2*   ln = s_lin[kk];

        float t2[4][4];
        #pragma unroll
        for (int n2 = 0; n2 < 4; n2++) {
            float p[4], q[4];
            {
                int s = 4 * n2;
                int2   la = ln[s],     lb = ln[s + 1];
                float4 ca = cf[s],     cb = cf[s + 1];
                float4 cn = cf[16 + 2 * n2];
                #pragma unroll
                for (int o = 0; o < 4; o++) {
                    float a0 = s_tile[bases[o] + la.x];
                    float b0 = s_tile[bases[o] + la.y];
                    float a1 = s_tile[bases[o] + lb.x];
                    float b1 = s_tile[bases[o] + lb.y];
                    p[o] = node_op(cn, node_op(ca, a0, b0), node_op(cb, a1, b1));
                }
            }
            {
                int s = 4 * n2 + 2;
                int2   la = ln[s],     lb = ln[s + 1];
                float4 ca = cf[s],     cb = cf[s + 1];
                float4 cn = cf[16 + 2 * n2 + 1];
                #pragma unroll
                for (int o = 0; o < 4; o++) {
                    float a0 = s_tile[bases[o] + la.x];
                    float b0 = s_tile[bases[o] + la.y];
                    float a1 = s_tile[bases[o] + lb.x];
                    float b1 = s_tile[bases[o] + lb.y];
                    q[o] = node_op(cn, node_op(ca, a0, b0), node_op(cb, a1, b1));
                }
            }
            float4 c2 = cf[24 + n2];
            #pragma unroll
            for (int o = 0; o < 4; o++)
                t2[n2][o] = node_op(c2, p[o], q[o]);
        }

        const float4 c3a = cf[28], c3b = cf[29], c4 = cf[30];
        if (lane < 30) {
            float* op = outb + kk * P_ + lane;
            #pragma unroll
            for (int o = 0; o < 4; o++) {
                float r = node_op(c4, node_op(c3a, t2[0][o], t2[1][o]),
                                      node_op(c3b, t2[2][o], t2[3][o]));
                int lw = warp + 8 * o;
                if (lw < 30) op[lw * 30] = r;
            }
        }
    }
}

extern "C" void kernel_launch(void* const* d_in, const int* in_sizes, int n_in,
                              void* d_out, int out_size)
{
    const float* x  = nullptr;
    const int*   ia = nullptr;
    const int*   ib = nullptr;
    const float* w0 = nullptr;
    const float* w1 = nullptr;
    const float* w2 = nullptr;
    const float* w3 = nullptr;
    const float* w4 = nullptr;

    for (int i = 0; i < n_in; i++) {
        int sz = in_sizes[i];
        switch (sz) {
            case 393216:   x  = (const float*)d_in[i]; break;   // 4*3*32^3
            case 27648000:                                      // K*P*S*4
                if (!ia) ia = (const int*)d_in[i];
                else     ib = (const int*)d_in[i];
                break;
            case 4096:     w0 = (const float*)d_in[i]; break;
            case 2048:     w1 = (const float*)d_in[i]; break;
            case 1024:     w2 = (const float*)d_in[i]; break;
            case 512:      w3 = (const float*)d_in[i]; break;
            case 256:      w4 = (const float*)d_in[i]; break;
            default: break;
        }
    }

    dim3 grid(30, K_ / KG, 4);
    logic_fused<<<grid, 256, DYN_BYTES>>>(x, ia, ib, w0, w1, w2, w3, w4,
                                          (float*)d_out);
}

// round 15
// speedup vs baseline: 1.6267x; 1.6267x over previous
#include <cuda_runtime.h>
#include <cuda_bf16.h>

#define K_ 16
#define P_ 27000

// Tile: x[b, c=0..2, h0:h0+3, 0:32, 0:32], strides c=3072,h=1024,w=32,d=1
#define TILE_F 9216
#define PAD_F  128                  // in-bounds pad for unclamped rows 30/31
#define DYN_BYTES ((TILE_F + PAD_F) * 4)   // 37376 B

__constant__ float c_MOPS[64] = {
    0,0,0,0,   0,0,0,1,   0,1,0,-1,  0,1,0,0,
    0,0,1,-1,  0,0,1,0,   0,1,1,-2,  0,1,1,-1,
    1,-1,-1,1, 1,-1,-1,2, 1,0,-1,0,  1,0,-1,1,
    1,-1,0,0,  1,-1,0,1,  1,0,0,-1,  1,0,0,0
};

// c0 + c1*a + c2*b + c3*a*b = fma(b, fma(c3,a,c2), fma(c1,a,c0))
__device__ __forceinline__ float node_op(float4 c, float a, float b) {
    return fmaf(b, fmaf(c.w, a, c.z), fmaf(c.y, a, c.x));
}
__device__ __forceinline__ float ldsf(unsigned a) {
    float v;
    asm("ld.shared.f32 %0, [%1];" : "=f"(v) : "r"(a));
    return v;
}

extern __shared__ float s_tile[];   // 9216 + 128 pad

__global__ __launch_bounds__(256, 4)
void logic_fused(const float* __restrict__ x,
                 const int* __restrict__ ia, const int* __restrict__ ib,
                 const float* __restrict__ w0, const float* __restrict__ w1,
                 const float* __restrict__ w2, const float* __restrict__ w3,
                 const float* __restrict__ w4,
                 float* __restrict__ out)
{
    __shared__ float4 s_coef[31];
    __shared__ int2   s_loff[16];           // leaf BYTE offsets (A, B)
    __shared__ unsigned long long s_mbar;   // TMA completion barrier

    const int h0 = blockIdx.x;   // 0..29
    const int k  = blockIdx.y;   // 0..15
    const int b  = blockIdx.z;   // 0..3
    const int t  = threadIdx.x;

    const unsigned mb = (unsigned)__cvta_generic_to_shared(&s_mbar);
    const unsigned tb0 = (unsigned)__cvta_generic_to_shared(s_tile);

    // ---- TMA: init barrier, issue 3 contiguous 12KB bulk copies ----
    if (t == 0) {
        asm volatile("mbarrier.init.shared.b64 [%0], 1;" :: "r"(mb) : "memory");
    }
    __syncthreads();
    if (t == 0) {
        asm volatile("mbarrier.arrive.expect_tx.shared.b64 _, [%0], %1;"
                     :: "r"(mb), "r"(TILE_F * 4) : "memory");
        const float* src = x + b * 98304 + h0 * 1024;   // x[b,0,h0,0,0]
        #pragma unroll
        for (int c = 0; c < 3; c++) {
            asm volatile(
                "cp.async.bulk.shared::cta.global.mbarrier::complete_tx::bytes "
                "[%0], [%1], %2, [%3];"
                :: "r"(tb0 + c * 3072 * 4), "l"(src + c * 32768),
                   "r"(3072 * 4), "r"(mb) : "memory");
        }
    }

    // ---- prep overlapped with TMA: tree coefficients (threads 0..30) ----
    if (t < 31) {
        const float* wp; int n;
        if      (t < 16) { wp = w0; n = t;      }
        else if (t < 24) { wp = w1; n = t - 16; }
        else if (t < 28) { wp = w2; n = t - 24; }
        else if (t < 30) { wp = w3; n = t - 28; }
        else             { wp = w4; n = 0;      }
        const float* row = wp + (n * K_ + k) * 16;
        float r[16];
        float m = -1e30f;
        #pragma unroll
        for (int o = 0; o < 16; o++) { r[o] = row[o]; m = fmaxf(m, r[o]); }
        float sum = 0.f;
        #pragma unroll
        for (int o = 0; o < 16; o++) { r[o] = __expf(r[o] - m); sum += r[o]; }
        float inv = 1.0f / sum;
        float c0 = 0.f, c1 = 0.f, c2 = 0.f, c3 = 0.f;
        #pragma unroll
        for (int o = 0; o < 16; o++) {
            float p = r[o] * inv;
            c0 = fmaf(p, c_MOPS[4*o + 0], c0);
            c1 = fmaf(p, c_MOPS[4*o + 1], c1);
            c2 = fmaf(p, c_MOPS[4*o + 2], c2);
            c3 = fmaf(p, c_MOPS[4*o + 3], c3);
        }
        s_coef[t] = make_float4(c0, c1, c2, c3);
    }
    // ---- prep: leaf byte offsets (threads 32..63) ----
    if (t >= 32 && t < 64) {
        int u = t - 32;
        const int* src = (u < 16) ? ia : ib;
        int s = u & 15;
        int base = (k * P_ * 16 + s) * 4;
        int h = src[base + 0];
        int w = src[base + 1];
        int d = src[base + 2];
        int c = src[base + 3];
        int off = (c * 3072 + h * 1024 + w * 32 + d) * 4;   // bytes
        if (u < 16) s_loff[s].x = off;
        else        s_loff[s].y = off;
    }

    __syncthreads();   // covers s_coef / s_loff writes

    // ---- wait for TMA data (acquire orders subsequent LDS) ----
    {
        unsigned done;
        asm volatile(
            "{\n\t.reg .pred p;\n\t"
            "mbarrier.try_wait.parity.acquire.cta.shared::cta.b64 p, [%1], 0;\n\t"
            "selp.b32 %0, 1, 0, p;\n\t}"
            : "=r"(done) : "r"(mb) : "memory");
        if (!done) {
            asm volatile(
                "{\n\t.reg .pred P1;\n\t"
                "W%=:\n\t"
                "mbarrier.try_wait.parity.acquire.cta.shared::cta.b64 P1, [%0], 0, 0x989680;\n\t"
                "@P1 bra.uni D%=;\n\t"
                "bra.uni W%=;\n\t"
                "D%=:\n\t}"
                :: "r"(mb) : "memory");
        }
    }

    // ---- compute: lane = d (clamped), rows warp+{0,8,16,24} via immediates ----
    const int lane = t & 31;
    const int warp = t >> 5;
    const int ld   = min(lane, 29);
    const unsigned tb = tb0 + 4u * (unsigned)(warp * 32 + ld);

    float t2[4][4];
    #pragma unroll
    for (int n2 = 0; n2 < 4; n2++) {
        float p[4], q[4];
        {
            int s = 4 * n2;
            unsigned aA0 = tb + (unsigned)s_loff[s].x;
            unsigned aB0 = tb + (unsigned)s_loff[s].y;
            unsigned aA1 = tb + (unsigned)s_loff[s + 1].x;
            unsigned aB1 = tb + (unsigned)s_loff[s + 1].y;
            float4 ca = s_coef[s], cb = s_coef[s + 1], cn = s_coef[16 + 2 * n2];
            #pragma unroll
            for (int o = 0; o < 4; o++) {
                float a0 = ldsf(aA0 + 1024u * o);
                float b0 = ldsf(aB0 + 1024u * o);
                float a1 = ldsf(aA1 + 1024u * o);
                float b1 = ldsf(aB1 + 1024u * o);
                p[o] = node_op(cn, node_op(ca, a0, b0), node_op(cb, a1, b1));
            }
        }
        {
            int s = 4 * n2 + 2;
            unsigned aA0 = tb + (unsigned)s_loff[s].x;
            unsigned aB0 = tb + (unsigned)s_loff[s].y;
            unsigned aA1 = tb + (unsigned)s_loff[s + 1].x;
            unsigned aB1 = tb + (unsigned)s_loff[s + 1].y;
            float4 ca = s_coef[s], cb = s_coef[s + 1], cn = s_coef[17 + 2 * n2];
            #pragma unroll
            for (int o = 0; o < 4; o++) {
                float a0 = ldsf(aA0 + 1024u * o);
                float b0 = ldsf(aB0 + 1024u * o);
                float a1 = ldsf(aA1 + 1024u * o);
                float b1 = ldsf(aB1 + 1024u * o);
                q[o] = node_op(cn, node_op(ca, a0, b0), node_op(cb, a1, b1));
            }
        }
        float4 c2 = s_coef[24 + n2];
        #pragma unroll
        for (int o = 0; o < 4; o++)
            t2[n2][o] = node_op(c2, p[o], q[o]);
    }

    const float4 c3a = s_coef[28], c3b = s_coef[29], c4 = s_coef[30];
    if (lane < 30) {
        float* op = out + (b * K_ + k) * P_ + h0 * 900 + warp * 30 + lane;
        #pragma unroll
        for (int o = 0; o < 4; o++) {
            float r = node_op(c4, node_op(c3a, t2[0][o], t2[1][o]),
                                  node_op(c3b, t2[2][o], t2[3][o]));
            if (o < 3 || warp < 6) op[o * 240] = r;   // rows warp+8o < 30
        }
    }
}

extern "C" void kernel_launch(void* const* d_in, const int* in_sizes, int n_in,
                              void* d_out, int out_size)
{
    const float* x  = nullptr;
    const int*   ia = nullptr;
    const int*   ib = nullptr;
    const float* w0 = nullptr;
    const float* w1 = nullptr;
    const float* w2 = nullptr;
    const float* w3 = nullptr;
    const float* w4 = nullptr;

    for (int i = 0; i < n_in; i++) {
        int sz = in_sizes[i];
        switch (sz) {
            case 393216:   x  = (const float*)d_in[i]; break;   // 4*3*32^3
            case 27648000:                                      // K*P*S*4
                if (!ia) ia = (const int*)d_in[i];
                else     ib = (const int*)d_in[i];
                break;
            case 4096:     w0 = (const float*)d_in[i]; break;
            case 2048:     w1 = (const float*)d_in[i]; break;
            case 1024:     w2 = (const float*)d_in[i]; break;
            case 512:      w3 = (const float*)d_in[i]; break;
            case 256:      w4 = (const float*)d_in[i]; break;
            default: break;
        }
    }

    dim3 grid(30, K_, 4);
    logic_fused<<<grid, 256, DYN_BYTES>>>(x, ia, ib, w0, w1, w2, w3, w4,
                                          (float*)d_out);
}